// round 11
// baseline (speedup 1.0000x reference)
#include <cuda_runtime.h>

#define B_ 32
#define T_ 256
#define D_ 512
#define N_ 8192   /* B*T query vectors  */
#define K_ 8192   /* codebook entries   */

__device__ float g_cnorm[K_];
__device__ int   g_counts[K_];
__device__ int   g_idx[N_];
__device__ float g_loss_partial[256];

// packed f32x2 FMA (Blackwell): d.lo += a.lo*b.lo ; d.hi += a.hi*b.hi
__device__ __forceinline__ void ffma2(unsigned long long &d,
                                      unsigned long long a,
                                      unsigned long long b) {
    asm("fma.rn.f32x2 %0, %1, %2, %0;" : "+l"(d) : "l"(a), "l"(b));
}

// monotone uint encoding of float (total order matches float compare)
__device__ __forceinline__ unsigned int fmono(float f) {
    unsigned int u = __float_as_uint(f);
    return u ^ ((unsigned int)((int)u >> 31) | 0x80000000u);
}

// ---------------------------------------------------------------------------
// K0: codebook squared norms + zero counts. One block per codebook row.
// ---------------------------------------------------------------------------
__global__ void k_prep(const float* __restrict__ cb) {
    const int k   = blockIdx.x;      // 8192
    const int tid = threadIdx.x;     // 128
    float4 v = *(const float4*)(cb + (size_t)k * D_ + tid * 4);
    float s = v.x * v.x + v.y * v.y + v.z * v.z + v.w * v.w;
    #pragma unroll
    for (int off = 16; off > 0; off >>= 1)
        s += __shfl_down_sync(0xffffffffu, s, off);
    __shared__ float red[4];
    if ((tid & 31) == 0) red[tid >> 5] = s;
    __syncthreads();
    if (tid == 0) {
        g_cnorm[k]  = red[0] + red[1] + red[2] + red[3];
        g_counts[k] = 0;
    }
}

// ---------------------------------------------------------------------------
// K1: fused distance GEMM + argmin.
// CTA: 64 queries x (loop over all 8192 codes in tiles of 512), BK=16.
// 256 threads (8 warps); warp w owns query rows [w*8, w*8+8); lane = col group.
// Micro-tile: 8 rows x 16 cols, columns packed pairwise into f32x2.
// ---------------------------------------------------------------------------
__global__ __launch_bounds__(256, 1) void k_argmin(
    const float* __restrict__ ze, const float* __restrict__ cb)
{
    __shared__ float2 As2[16][64];    // A duplicated into both f32x2 halves
    __shared__ float  Bs[16][514];    // +2 pad: conflict-free fill stores

    const int tid    = threadIdx.x;
    const int trow   = tid >> 5;      // warp id = row group
    const int tcol   = tid & 31;      // lane    = col group
    const int m_base = blockIdx.x * 64;
    const int bb     = m_base >> 8;   // batch index (64 | 256)
    const int t0     = m_base & 255;
    const float* zbase = ze + (size_t)bb * (D_ * T_) + t0;

    unsigned long long best[8];
    #pragma unroll
    for (int r = 0; r < 8; r++) best[r] = 0xFFFFFFFFFFFFFFFFull;

    #pragma unroll 1
    for (int nt = 0; nt < K_ / 512; ++nt) {
        const int n_base = nt * 512;

        unsigned long long acc[8][8];
        #pragma unroll
        for (int r = 0; r < 8; r++)
            #pragma unroll
            for (int j = 0; j < 8; j++) acc[r][j] = 0ull;

        #pragma unroll 1
        for (int ck = 0; ck < D_ / 16; ++ck) {
            const int kk = ck * 16;
            __syncthreads();
            // --- fill A tile: 16 d x 64 m (strided gmem reads, coalesced in m)
            #pragma unroll
            for (int i = 0; i < 4; i++) {
                int id = tid + i * 256;
                int d  = id >> 6, m = id & 63;
                float v = zbase[(size_t)(kk + d) * T_ + m];
                As2[d][m] = make_float2(v, v);
            }
            // --- fill B tile: 512 codes x 16 d (float4 per code row)
            // 512 codes * 4 float4-groups = 2048 ids -> 8 passes of 256 threads
            #pragma unroll
            for (int i = 0; i < 8; i++) {
                int id = tid + i * 256;
                int c  = id >> 2, q = id & 3;
                const float4 v = *(const float4*)(cb + (size_t)(n_base + c) * D_ + kk + q * 4);
                Bs[q * 4 + 0][c] = v.x;
                Bs[q * 4 + 1][c] = v.y;
                Bs[q * 4 + 2][c] = v.z;
                Bs[q * 4 + 3][c] = v.w;
            }
            __syncthreads();

            // --- 16 rank-1 updates, 64 FFMA2 each
            #pragma unroll
            for (int k = 0; k < 16; ++k) {
                unsigned long long a[8], b[8];
                const unsigned long long* ap =
                    (const unsigned long long*)&As2[k][trow * 8];
                #pragma unroll
                for (int r = 0; r < 8; r++) a[r] = ap[r];
                #pragma unroll
                for (int j = 0; j < 8; j++)
                    b[j] = *(const unsigned long long*)&Bs[k][2 * (tcol + 32 * j)];
                #pragma unroll
                for (int r = 0; r < 8; r++)
                    #pragma unroll
                    for (int j = 0; j < 8; j++)
                        ffma2(acc[r][j], a[r], b[j]);
            }
        }

        // --- epilogue for this 512-code tile: score = ||c||^2 - 2*dot
        #pragma unroll
        for (int j = 0; j < 8; j++) {
            const int c2 = tcol + 32 * j;
            const int c  = n_base + 2 * c2;
            const float2 cn = *(const float2*)&g_cnorm[c];
            #pragma unroll
            for (int r = 0; r < 8; r++) {
                float lo = __uint_as_float((unsigned int)(acc[r][j]));
                float hi = __uint_as_float((unsigned int)(acc[r][j] >> 32));
                float s0 = cn.x - 2.0f * lo;
                float s1 = cn.y - 2.0f * hi;
                unsigned long long p0 =
                    ((unsigned long long)fmono(s0) << 32) | (unsigned int)c;
                unsigned long long p1 =
                    ((unsigned long long)fmono(s1) << 32) | (unsigned int)(c + 1);
                if (p0 < best[r]) best[r] = p0;
                if (p1 < best[r]) best[r] = p1;
            }
        }
    }

    // --- warp-level min-reduce (all lanes of a warp share the same 8 rows)
    #pragma unroll
    for (int r = 0; r < 8; r++) {
        unsigned long long v = best[r];
        #pragma unroll
        for (int off = 16; off > 0; off >>= 1) {
            unsigned long long o = __shfl_down_sync(0xffffffffu, v, off);
            if (o < v) v = o;
        }
        if (tcol == 0)
            g_idx[m_base + trow * 8 + r] = (int)(v & 0xFFFFFFFFull);
    }
}

// ---------------------------------------------------------------------------
// K2: gather z_q (transposed back to (b,d,t)), loss partials, counts.
// grid (32 b, 8 d-chunks) x 256 t-threads.
// ---------------------------------------------------------------------------
__global__ void k_gather(const float* __restrict__ ze,
                         const float* __restrict__ cb,
                         float* __restrict__ out)
{
    const int b  = blockIdx.x;
    const int dc = blockIdx.y;
    const int t  = threadIdx.x;        // 256
    const int n  = b * T_ + t;
    const int i  = g_idx[n];
    if (dc == 0) atomicAdd(&g_counts[i], 1);

    const float* crow = cb + (size_t)i * D_;
    const float* zb   = ze  + (size_t)b * (D_ * T_) + t;
    float*       ob   = out + (size_t)b * (D_ * T_) + t;

    float s = 0.f;
    const int d0 = dc * 64;
    #pragma unroll 8
    for (int d = d0; d < d0 + 64; ++d) {
        float c = __ldg(crow + d);
        float z = zb[(size_t)d * T_];
        ob[(size_t)d * T_] = c;
        float df = c - z;
        s += df * df;
    }

    #pragma unroll
    for (int off = 16; off > 0; off >>= 1)
        s += __shfl_down_sync(0xffffffffu, s, off);
    __shared__ float red[8];
    if ((t & 31) == 0) red[t >> 5] = s;
    __syncthreads();
    if (t == 0) {
        float tot = 0.f;
        #pragma unroll
        for (int w = 0; w < 8; w++) tot += red[w];
        g_loss_partial[b * 8 + dc] = tot;
    }
}

// ---------------------------------------------------------------------------
// K3: finalize vq_loss and perplexity. Single block.
// ---------------------------------------------------------------------------
__global__ void k_final(float* __restrict__ out, int out_size)
{
    const int tid = threadIdx.x;   // 1024
    float ent = 0.f;
    for (int k = tid; k < K_; k += 1024) {
        float p = (float)g_counts[k] * (1.0f / (float)N_);
        ent += p * logf(p + 1e-10f);
    }
    #pragma unroll
    for (int off = 16; off > 0; off >>= 1)
        ent += __shfl_down_sync(0xffffffffu, ent, off);
    __shared__ float red[32];
    if ((tid & 31) == 0) red[tid >> 5] = ent;
    __syncthreads();
    if (tid < 32) {
        float v = red[tid];
        #pragma unroll
        for (int off = 16; off > 0; off >>= 1)
            v += __shfl_down_sync(0xffffffffu, v, off);
        if (tid == 0) {
            float ls = 0.f;
            for (int i = 0; i < 256; i++) ls += g_loss_partial[i];
            out[out_size - 2] = 0.25f * ls / (float)((size_t)N_ * D_); // vq_loss
            out[out_size - 1] = expf(-v);                              // perplexity
        }
    }
}

// ---------------------------------------------------------------------------
extern "C" void kernel_launch(void* const* d_in, const int* in_sizes, int n_in,
                              void* d_out, int out_size)
{
    const float* ze = (const float*)d_in[0];   // z_e      (32, 512, 256)
    const float* cb = (const float*)d_in[1];   // codebook (8192, 512)
    float* out = (float*)d_out;

    k_prep  <<<K_, 128>>>(cb);
    k_argmin<<<N_ / 64, 256>>>(ze, cb);
    k_gather<<<dim3(B_, 8), 256>>>(ze, cb, out);
    k_final <<<1, 1024>>>(out, out_size);
}

// round 12
// speedup vs baseline: 1.0013x; 1.0013x over previous
#include <cuda_runtime.h>

#define B_ 32
#define T_ 256
#define D_ 512
#define N_ 8192   /* B*T query vectors  */
#define K_ 8192   /* codebook entries   */

__device__ float g_cnorm[K_];
__device__ int   g_counts[K_];
__device__ int   g_idx[N_];
__device__ float g_loss_partial[256];

// packed f32x2 FMA (Blackwell): d.lo += a.lo*b.lo ; d.hi += a.hi*b.hi
__device__ __forceinline__ void ffma2(unsigned long long &d,
                                      unsigned long long a,
                                      unsigned long long b) {
    asm("fma.rn.f32x2 %0, %1, %2, %0;" : "+l"(d) : "l"(a), "l"(b));
}

// monotone uint encoding of float (total order matches float compare)
__device__ __forceinline__ unsigned int fmono(float f) {
    unsigned int u = __float_as_uint(f);
    return u ^ ((unsigned int)((int)u >> 31) | 0x80000000u);
}

// ---------------------------------------------------------------------------
// K0: codebook squared norms + zero counts. One block per codebook row.
// ---------------------------------------------------------------------------
__global__ void k_prep(const float* __restrict__ cb) {
    const int k   = blockIdx.x;      // 8192
    const int tid = threadIdx.x;     // 128
    float4 v = *(const float4*)(cb + (size_t)k * D_ + tid * 4);
    float s = v.x * v.x + v.y * v.y + v.z * v.z + v.w * v.w;
    #pragma unroll
    for (int off = 16; off > 0; off >>= 1)
        s += __shfl_down_sync(0xffffffffu, s, off);
    __shared__ float red[4];
    if ((tid & 31) == 0) red[tid >> 5] = s;
    __syncthreads();
    if (tid == 0) {
        g_cnorm[k]  = red[0] + red[1] + red[2] + red[3];
        g_counts[k] = 0;
    }
}

// ---------------------------------------------------------------------------
// K1: fused distance GEMM + argmin.
// CTA: 64 queries x (loop over all 8192 codes in tiles of 512), BK=16.
// 256 threads (8 warps); warp w owns query rows [w*8, w*8+8); lane = col group.
// Micro-tile: 8 rows x 16 cols, columns packed pairwise into f32x2.
// ---------------------------------------------------------------------------
__global__ __launch_bounds__(256, 1) void k_argmin(
    const float* __restrict__ ze, const float* __restrict__ cb)
{
    __shared__ float2 As2[16][64];    // A duplicated into both f32x2 halves
    __shared__ float  Bs[16][514];    // +2 pad: conflict-free fill stores

    const int tid    = threadIdx.x;
    const int trow   = tid >> 5;      // warp id = row group
    const int tcol   = tid & 31;      // lane    = col group
    const int m_base = blockIdx.x * 64;
    const int bb     = m_base >> 8;   // batch index (64 | 256)
    const int t0     = m_base & 255;
    const float* zbase = ze + (size_t)bb * (D_ * T_) + t0;

    unsigned long long best[8];
    #pragma unroll
    for (int r = 0; r < 8; r++) best[r] = 0xFFFFFFFFFFFFFFFFull;

    #pragma unroll 1
    for (int nt = 0; nt < K_ / 512; ++nt) {
        const int n_base = nt * 512;

        unsigned long long acc[8][8];
        #pragma unroll
        for (int r = 0; r < 8; r++)
            #pragma unroll
            for (int j = 0; j < 8; j++) acc[r][j] = 0ull;

        #pragma unroll 1
        for (int ck = 0; ck < D_ / 16; ++ck) {
            const int kk = ck * 16;
            __syncthreads();
            // --- fill A tile: 16 d x 64 m (strided gmem reads, coalesced in m)
            #pragma unroll
            for (int i = 0; i < 4; i++) {
                int id = tid + i * 256;
                int d  = id >> 6, m = id & 63;
                float v = zbase[(size_t)(kk + d) * T_ + m];
                As2[d][m] = make_float2(v, v);
            }
            // --- fill B tile: 512 codes x 16 d (float4 per code row)
            // 512 codes * 4 float4-groups = 2048 ids -> 8 passes of 256 threads
            #pragma unroll
            for (int i = 0; i < 8; i++) {
                int id = tid + i * 256;
                int c  = id >> 2, q = id & 3;
                const float4 v = *(const float4*)(cb + (size_t)(n_base + c) * D_ + kk + q * 4);
                Bs[q * 4 + 0][c] = v.x;
                Bs[q * 4 + 1][c] = v.y;
                Bs[q * 4 + 2][c] = v.z;
                Bs[q * 4 + 3][c] = v.w;
            }
            __syncthreads();

            // --- 16 rank-1 updates, 64 FFMA2 each
            #pragma unroll
            for (int k = 0; k < 16; ++k) {
                unsigned long long a[8], b[8];
                const unsigned long long* ap =
                    (const unsigned long long*)&As2[k][trow * 8];
                #pragma unroll
                for (int r = 0; r < 8; r++) a[r] = ap[r];
                #pragma unroll
                for (int j = 0; j < 8; j++)
                    b[j] = *(const unsigned long long*)&Bs[k][2 * (tcol + 32 * j)];
                #pragma unroll
                for (int r = 0; r < 8; r++)
                    #pragma unroll
                    for (int j = 0; j < 8; j++)
                        ffma2(acc[r][j], a[r], b[j]);
            }
        }

        // --- epilogue for this 512-code tile: score = ||c||^2 - 2*dot
        #pragma unroll
        for (int j = 0; j < 8; j++) {
            const int c2 = tcol + 32 * j;
            const int c  = n_base + 2 * c2;
            const float2 cn = *(const float2*)&g_cnorm[c];
            #pragma unroll
            for (int r = 0; r < 8; r++) {
                float lo = __uint_as_float((unsigned int)(acc[r][j]));
                float hi = __uint_as_float((unsigned int)(acc[r][j] >> 32));
                float s0 = cn.x - 2.0f * lo;
                float s1 = cn.y - 2.0f * hi;
                unsigned long long p0 =
                    ((unsigned long long)fmono(s0) << 32) | (unsigned int)c;
                unsigned long long p1 =
                    ((unsigned long long)fmono(s1) << 32) | (unsigned int)(c + 1);
                if (p0 < best[r]) best[r] = p0;
                if (p1 < best[r]) best[r] = p1;
            }
        }
    }

    // --- warp-level min-reduce (all lanes of a warp share the same 8 rows)
    #pragma unroll
    for (int r = 0; r < 8; r++) {
        unsigned long long v = best[r];
        #pragma unroll
        for (int off = 16; off > 0; off >>= 1) {
            unsigned long long o = __shfl_down_sync(0xffffffffu, v, off);
            if (o < v) v = o;
        }
        if (tcol == 0)
            g_idx[m_base + trow * 8 + r] = (int)(v & 0xFFFFFFFFull);
    }
}

// ---------------------------------------------------------------------------
// K2: gather z_q (transposed back to (b,d,t)), loss partials, counts.
// grid (32 b, 8 d-chunks) x 256 t-threads.
// ---------------------------------------------------------------------------
__global__ void k_gather(const float* __restrict__ ze,
                         const float* __restrict__ cb,
                         float* __restrict__ out)
{
    const int b  = blockIdx.x;
    const int dc = blockIdx.y;
    const int t  = threadIdx.x;        // 256
    const int n  = b * T_ + t;
    const int i  = g_idx[n];
    if (dc == 0) atomicAdd(&g_counts[i], 1);

    const float* crow = cb + (size_t)i * D_;
    const float* zb   = ze  + (size_t)b * (D_ * T_) + t;
    float*       ob   = out + (size_t)b * (D_ * T_) + t;

    float s = 0.f;
    const int d0 = dc * 64;
    #pragma unroll 8
    for (int d = d0; d < d0 + 64; ++d) {
        float c = __ldg(crow + d);
        float z = zb[(size_t)d * T_];
        ob[(size_t)d * T_] = c;
        float df = c - z;
        s += df * df;
    }

    #pragma unroll
    for (int off = 16; off > 0; off >>= 1)
        s += __shfl_down_sync(0xffffffffu, s, off);
    __shared__ float red[8];
    if ((t & 31) == 0) red[t >> 5] = s;
    __syncthreads();
    if (t == 0) {
        float tot = 0.f;
        #pragma unroll
        for (int w = 0; w < 8; w++) tot += red[w];
        g_loss_partial[b * 8 + dc] = tot;
    }
}

// ---------------------------------------------------------------------------
// K3: finalize vq_loss and perplexity. Single block.
// ---------------------------------------------------------------------------
__global__ void k_final(float* __restrict__ out, int out_size)
{
    const int tid = threadIdx.x;   // 1024
    float ent = 0.f;
    for (int k = tid; k < K_; k += 1024) {
        float p = (float)g_counts[k] * (1.0f / (float)N_);
        ent += p * logf(p + 1e-10f);
    }
    #pragma unroll
    for (int off = 16; off > 0; off >>= 1)
        ent += __shfl_down_sync(0xffffffffu, ent, off);
    __shared__ float red[32];
    if ((tid & 31) == 0) red[tid >> 5] = ent;
    __syncthreads();
    if (tid < 32) {
        float v = red[tid];
        #pragma unroll
        for (int off = 16; off > 0; off >>= 1)
            v += __shfl_down_sync(0xffffffffu, v, off);
        if (tid == 0) {
            float ls = 0.f;
            for (int i = 0; i < 256; i++) ls += g_loss_partial[i];
            out[out_size - 2] = 0.25f * ls / (float)((size_t)N_ * D_); // vq_loss
            out[out_size - 1] = expf(-v);                              // perplexity
        }
    }
}

// ---------------------------------------------------------------------------
extern "C" void kernel_launch(void* const* d_in, const int* in_sizes, int n_in,
                              void* d_out, int out_size)
{
    const float* ze = (const float*)d_in[0];   // z_e      (32, 512, 256)
    const float* cb = (const float*)d_in[1];   // codebook (8192, 512)
    float* out = (float*)d_out;

    k_prep  <<<K_, 128>>>(cb);
    k_argmin<<<N_ / 64, 256>>>(ze, cb);
    k_gather<<<dim3(B_, 8), 256>>>(ze, cb, out);
    k_final <<<1, 1024>>>(out, out_size);
}

// round 13
// speedup vs baseline: 1.0053x; 1.0040x over previous
#include <cuda_runtime.h>

#define B_ 32
#define T_ 256
#define D_ 512
#define N_ 8192   /* B*T query vectors  */
#define K_ 8192   /* codebook entries   */

__device__ float g_cnorm[K_];
__device__ int   g_counts[K_];
__device__ int   g_idx[N_];
__device__ float g_loss_partial[256];

// packed f32x2 FMA (Blackwell): d.lo += a.lo*b.lo ; d.hi += a.hi*b.hi
__device__ __forceinline__ void ffma2(unsigned long long &d,
                                      unsigned long long a,
                                      unsigned long long b) {
    asm("fma.rn.f32x2 %0, %1, %2, %0;" : "+l"(d) : "l"(a), "l"(b));
}

// monotone uint encoding of float (total order matches float compare)
__device__ __forceinline__ unsigned int fmono(float f) {
    unsigned int u = __float_as_uint(f);
    return u ^ ((unsigned int)((int)u >> 31) | 0x80000000u);
}

// ---------------------------------------------------------------------------
// K0: codebook squared norms + zero counts. One block per codebook row.
// ---------------------------------------------------------------------------
__global__ void k_prep(const float* __restrict__ cb) {
    const int k   = blockIdx.x;      // 8192
    const int tid = threadIdx.x;     // 128
    float4 v = *(const float4*)(cb + (size_t)k * D_ + tid * 4);
    float s = v.x * v.x + v.y * v.y + v.z * v.z + v.w * v.w;
    #pragma unroll
    for (int off = 16; off > 0; off >>= 1)
        s += __shfl_down_sync(0xffffffffu, s, off);
    __shared__ float red[4];
    if ((tid & 31) == 0) red[tid >> 5] = s;
    __syncthreads();
    if (tid == 0) {
        g_cnorm[k]  = red[0] + red[1] + red[2] + red[3];
        g_counts[k] = 0;
    }
}

// ---------------------------------------------------------------------------
// K1: fused distance GEMM + argmin.
// CTA: 64 queries x (loop over all 8192 codes in tiles of 512), BK=16.
// 256 threads (8 warps); warp w owns query rows [w*8, w*8+8); lane = col group.
// Micro-tile: 8 rows x 16 cols, columns packed pairwise into f32x2.
// ---------------------------------------------------------------------------
__global__ __launch_bounds__(256, 1) void k_argmin(
    const float* __restrict__ ze, const float* __restrict__ cb)
{
    __shared__ float2 As2[16][64];    // A duplicated into both f32x2 halves
    __shared__ float  Bs[16][514];    // +2 pad: conflict-free fill stores

    const int tid    = threadIdx.x;
    const int trow   = tid >> 5;      // warp id = row group
    const int tcol   = tid & 31;      // lane    = col group
    const int m_base = blockIdx.x * 64;
    const int bb     = m_base >> 8;   // batch index (64 | 256)
    const int t0     = m_base & 255;
    const float* zbase = ze + (size_t)bb * (D_ * T_) + t0;

    unsigned long long best[8];
    #pragma unroll
    for (int r = 0; r < 8; r++) best[r] = 0xFFFFFFFFFFFFFFFFull;

    #pragma unroll 1
    for (int nt = 0; nt < K_ / 512; ++nt) {
        const int n_base = nt * 512;

        unsigned long long acc[8][8];
        #pragma unroll
        for (int r = 0; r < 8; r++)
            #pragma unroll
            for (int j = 0; j < 8; j++) acc[r][j] = 0ull;

        #pragma unroll 1
        for (int ck = 0; ck < D_ / 16; ++ck) {
            const int kk = ck * 16;
            __syncthreads();
            // --- fill A tile: 16 d x 64 m (strided gmem reads, coalesced in m)
            #pragma unroll
            for (int i = 0; i < 4; i++) {
                int id = tid + i * 256;
                int d  = id >> 6, m = id & 63;
                float v = zbase[(size_t)(kk + d) * T_ + m];
                As2[d][m] = make_float2(v, v);
            }
            // --- fill B tile: 512 codes x 16 d (float4 per code row)
            // 512 codes * 4 float4-groups = 2048 ids -> 8 passes of 256 threads
            #pragma unroll
            for (int i = 0; i < 8; i++) {
                int id = tid + i * 256;
                int c  = id >> 2, q = id & 3;
                const float4 v = *(const float4*)(cb + (size_t)(n_base + c) * D_ + kk + q * 4);
                Bs[q * 4 + 0][c] = v.x;
                Bs[q * 4 + 1][c] = v.y;
                Bs[q * 4 + 2][c] = v.z;
                Bs[q * 4 + 3][c] = v.w;
            }
            __syncthreads();

            // --- 16 rank-1 updates, 64 FFMA2 each
            #pragma unroll
            for (int k = 0; k < 16; ++k) {
                unsigned long long a[8], b[8];
                const unsigned long long* ap =
                    (const unsigned long long*)&As2[k][trow * 8];
                #pragma unroll
                for (int r = 0; r < 8; r++) a[r] = ap[r];
                #pragma unroll
                for (int j = 0; j < 8; j++)
                    b[j] = *(const unsigned long long*)&Bs[k][2 * (tcol + 32 * j)];
                #pragma unroll
                for (int r = 0; r < 8; r++)
                    #pragma unroll
                    for (int j = 0; j < 8; j++)
                        ffma2(acc[r][j], a[r], b[j]);
            }
        }

        // --- epilogue for this 512-code tile: score = ||c||^2 - 2*dot
        #pragma unroll
        for (int j = 0; j < 8; j++) {
            const int c2 = tcol + 32 * j;
            const int c  = n_base + 2 * c2;
            const float2 cn = *(const float2*)&g_cnorm[c];
            #pragma unroll
            for (int r = 0; r < 8; r++) {
                float lo = __uint_as_float((unsigned int)(acc[r][j]));
                float hi = __uint_as_float((unsigned int)(acc[r][j] >> 32));
                float s0 = cn.x - 2.0f * lo;
                float s1 = cn.y - 2.0f * hi;
                unsigned long long p0 =
                    ((unsigned long long)fmono(s0) << 32) | (unsigned int)c;
                unsigned long long p1 =
                    ((unsigned long long)fmono(s1) << 32) | (unsigned int)(c + 1);
                if (p0 < best[r]) best[r] = p0;
                if (p1 < best[r]) best[r] = p1;
            }
        }
    }

    // --- warp-level min-reduce (all lanes of a warp share the same 8 rows)
    #pragma unroll
    for (int r = 0; r < 8; r++) {
        unsigned long long v = best[r];
        #pragma unroll
        for (int off = 16; off > 0; off >>= 1) {
            unsigned long long o = __shfl_down_sync(0xffffffffu, v, off);
            if (o < v) v = o;
        }
        if (tcol == 0)
            g_idx[m_base + trow * 8 + r] = (int)(v & 0xFFFFFFFFull);
    }
}

// ---------------------------------------------------------------------------
// K2: gather z_q (transposed back to (b,d,t)), loss partials, counts.
// grid (32 b, 8 d-chunks) x 256 t-threads.
// ---------------------------------------------------------------------------
__global__ void k_gather(const float* __restrict__ ze,
                         const float* __restrict__ cb,
                         float* __restrict__ out)
{
    const int b  = blockIdx.x;
    const int dc = blockIdx.y;
    const int t  = threadIdx.x;        // 256
    const int n  = b * T_ + t;
    const int i  = g_idx[n];
    if (dc == 0) atomicAdd(&g_counts[i], 1);

    const float* crow = cb + (size_t)i * D_;
    const float* zb   = ze  + (size_t)b * (D_ * T_) + t;
    float*       ob   = out + (size_t)b * (D_ * T_) + t;

    float s = 0.f;
    const int d0 = dc * 64;
    #pragma unroll 8
    for (int d = d0; d < d0 + 64; ++d) {
        float c = __ldg(crow + d);
        float z = zb[(size_t)d * T_];
        ob[(size_t)d * T_] = c;
        float df = c - z;
        s += df * df;
    }

    #pragma unroll
    for (int off = 16; off > 0; off >>= 1)
        s += __shfl_down_sync(0xffffffffu, s, off);
    __shared__ float red[8];
    if ((t & 31) == 0) red[t >> 5] = s;
    __syncthreads();
    if (t == 0) {
        float tot = 0.f;
        #pragma unroll
        for (int w = 0; w < 8; w++) tot += red[w];
        g_loss_partial[b * 8 + dc] = tot;
    }
}

// ---------------------------------------------------------------------------
// K3: finalize vq_loss and perplexity. Single block.
// ---------------------------------------------------------------------------
__global__ void k_final(float* __restrict__ out, int out_size)
{
    const int tid = threadIdx.x;   // 1024
    float ent = 0.f;
    for (int k = tid; k < K_; k += 1024) {
        float p = (float)g_counts[k] * (1.0f / (float)N_);
        ent += p * logf(p + 1e-10f);
    }
    #pragma unroll
    for (int off = 16; off > 0; off >>= 1)
        ent += __shfl_down_sync(0xffffffffu, ent, off);
    __shared__ float red[32];
    if ((tid & 31) == 0) red[tid >> 5] = ent;
    __syncthreads();
    if (tid < 32) {
        float v = red[tid];
        #pragma unroll
        for (int off = 16; off > 0; off >>= 1)
            v += __shfl_down_sync(0xffffffffu, v, off);
        if (tid == 0) {
            float ls = 0.f;
            for (int i = 0; i < 256; i++) ls += g_loss_partial[i];
            out[out_size - 2] = 0.25f * ls / (float)((size_t)N_ * D_); // vq_loss
            out[out_size - 1] = expf(-v);                              // perplexity
        }
    }
}

// ---------------------------------------------------------------------------
extern "C" void kernel_launch(void* const* d_in, const int* in_sizes, int n_in,
                              void* d_out, int out_size)
{
    const float* ze = (const float*)d_in[0];   // z_e      (32, 512, 256)
    const float* cb = (const float*)d_in[1];   // codebook (8192, 512)
    float* out = (float*)d_out;

    k_prep  <<<K_, 128>>>(cb);
    k_argmin<<<N_ / 64, 256>>>(ze, cb);
    k_gather<<<dim3(B_, 8), 256>>>(ze, cb, out);
    k_final <<<1, 1024>>>(out, out_size);
}